// round 8
// baseline (speedup 1.0000x reference)
#include <cuda_runtime.h>

#define NN 100000
#define EE 1600000
#define NPAD (98 * 1024)          // NN padded to scan granularity (98 blocks x 1024)

// Static device scratch (allocation-free per harness rules)
__device__ float g_rs2[2][NN];    // double-buffered staged value ns*r_k
__device__ float g_ns[NN];        // out_deg^-1/2
__device__ float g_nd[NN];        // in_deg^-1/2
__device__ int2  g_edge[EE];      // decoded (src,dst) in input order
__device__ int   g_ssort[EE];     // src indices, sorted by dst (CSR adjacency)
__device__ int   g_cs[NPAD];      // src histogram (out-degree)
__device__ int   g_cd[NPAD];      // dst histogram (in-degree = CSR row length)
__device__ int   g_cur[NPAD];     // running offsets for permute
__device__ int   g_row[NPAD];     // CSR row starts (exclusive scan of g_cd)
__device__ int   g_part[98];      // per-block partial sums
__device__ int   g_base[98];      // exclusive block bases
__device__ int   g_tick;          // last-block ticket
__device__ float g_scal[8];       // s0..s5, w
__device__ int   g_is64;

// ---------------------------------------------------------------------------
// Fused setup: block 0 = collapse linear channel path to scalars; block 1 =
// index dtype probe (first 256 elems as u64: 2KB read, safe for either dtype;
// genuine int64 indices are all < NN, aliased int32 pairs exceed NN w.p. ~1);
// blocks 2.. = zero histograms + ticket.
// ---------------------------------------------------------------------------
__global__ void k_setup(const unsigned long long* __restrict__ srcp,
                        const float* __restrict__ W0, const float* __restrict__ b0,
                        const float* __restrict__ W1, const float* __restrict__ b1,
                        const float* __restrict__ W2, const float* __restrict__ b2,
                        const float* __restrict__ W3, const float* __restrict__ b3,
                        const float* __restrict__ W4, const float* __restrict__ b4,
                        const float* __restrict__ W5, const float* __restrict__ b5) {
    int t = threadIdx.x;
    if (blockIdx.x == 0) {
        __shared__ float u5[32], u4[64], u3[128], u2[64], u1[32];
        if (t < 32) u5[t] = W5[t];
        __syncthreads();
        if (t < 64) { float s = 0.f; for (int j = 0; j < 32; j++) s += W4[t*32+j]*u5[j]; u4[t] = s; }
        __syncthreads();
        if (t < 128){ float s = 0.f; for (int j = 0; j < 64; j++) s += W3[t*64+j]*u4[j]; u3[t] = s; }
        __syncthreads();
        if (t < 64) { float s = 0.f; for (int j = 0; j < 128;j++) s += W2[t*128+j]*u3[j]; u2[t] = s; }
        __syncthreads();
        if (t < 32) { float s = 0.f; for (int j = 0; j < 64; j++) s += W1[t*64+j]*u2[j]; u1[t] = s; }
        __syncthreads();
        if (t == 0) {
            float w = 0.f, s0 = 0.f;
            for (int j = 0; j < 32; j++)  { w += W0[j]*u1[j]; s0 += b0[j]*u1[j]; }
            float s1 = 0.f; for (int j = 0; j < 64;  j++) s1 += b1[j]*u2[j];
            float s2 = 0.f; for (int j = 0; j < 128; j++) s2 += b2[j]*u3[j];
            float s3 = 0.f; for (int j = 0; j < 64;  j++) s3 += b3[j]*u4[j];
            float s4 = 0.f; for (int j = 0; j < 32;  j++) s4 += b4[j]*u5[j];
            g_scal[0]=s0; g_scal[1]=s1; g_scal[2]=s2; g_scal[3]=s3; g_scal[4]=s4;
            g_scal[5]=b5[0]; g_scal[6]=w;
            g_tick = 0;
        }
    } else if (blockIdx.x == 1) {
        int bad = (srcp[t] >= (unsigned long long)NN) ? 1 : 0;
        int any = __syncthreads_or(bad);
        if (t == 0) g_is64 = any ? 0 : 1;
    } else {
        int n = (blockIdx.x - 2) * blockDim.x + t;     // 0 .. NPAD/4-1
        if (n < NPAD / 4) {
            int4 zi = make_int4(0, 0, 0, 0);
            reinterpret_cast<int4*>(g_cs)[n] = zi;
            reinterpret_cast<int4*>(g_cd)[n] = zi;
        }
    }
}

// Decode 1 edge/thread, clamp, store packed int2, build both histograms.
__global__ void k_edges(const void* __restrict__ srcv,
                        const void* __restrict__ dstv) {
    int e = blockIdx.x * blockDim.x + threadIdx.x;
    if (e < EE) {
        long long sl, dl;
        if (g_is64) {
            sl = ((const long long*)srcv)[e];
            dl = ((const long long*)dstv)[e];
        } else {
            sl = ((const int*)srcv)[e];
            dl = ((const int*)dstv)[e];
        }
        int s = (sl < 0) ? 0 : (sl >= NN ? NN - 1 : (int)sl);
        int d = (dl < 0) ? 0 : (dl >= NN ? NN - 1 : (int)dl);
        g_edge[e] = make_int2(s, d);
        atomicAdd(&g_cs[s], 1);
        atomicAdd(&g_cd[d], 1);
    }
}

// Fused scan stage 1+2: per-block sums of g_cd; the LAST block to finish
// exclusive-scans the 98 partials into g_base.
__global__ void k_scanA() {
    int t = threadIdx.x, b = blockIdx.x;
    int4 c = reinterpret_cast<const int4*>(g_cd)[b * 256 + t];
    int v = c.x + c.y + c.z + c.w;
    __shared__ int sh[256];
    sh[t] = v; __syncthreads();
    for (int off = 128; off > 0; off >>= 1) {
        if (t < off) sh[t] += sh[t + off];
        __syncthreads();
    }
    __shared__ int is_last;
    if (t == 0) {
        g_part[b] = sh[0];
        __threadfence();
        is_last = (atomicAdd(&g_tick, 1) == gridDim.x - 1);
    }
    __syncthreads();
    if (is_last) {
        __shared__ int sp[128];
        int pv = (t < 98) ? g_part[t] : 0;
        if (t < 128) sp[t] = pv;
        __syncthreads();
        for (int off = 1; off < 128; off <<= 1) {
            int a = (t < 128 && t >= off) ? sp[t - off] : 0;
            __syncthreads();
            if (t < 128) sp[t] += a;
            __syncthreads();
        }
        if (t < 98) g_base[t] = sp[t] - pv;    // exclusive
    }
}

// Scan stage 3: per-element exclusive offsets of g_cd -> g_cur and g_row (CSR starts).
__global__ void k_scan3() {
    int t = threadIdx.x, b = blockIdx.x;
    int4 c = reinterpret_cast<const int4*>(g_cd)[b * 256 + t];
    int tsum = c.x + c.y + c.z + c.w;
    __shared__ int sh[256];
    sh[t] = tsum; __syncthreads();
    for (int off = 1; off < 256; off <<= 1) {
        int a = (t >= off) ? sh[t - off] : 0;
        __syncthreads();
        sh[t] += a;
        __syncthreads();
    }
    int base = g_base[b] + sh[t] - tsum;       // exclusive across threads
    int4 o;
    o.x = base;
    o.y = o.x + c.x;
    o.z = o.y + c.y;
    o.w = o.z + c.z;
    reinterpret_cast<int4*>(g_cur)[b * 256 + t] = o;
    reinterpret_cast<int4*>(g_row)[b * 256 + t] = o;
}

// Permute: write src index into dst-sorted CSR adjacency (4B random writes).
__global__ void k_perm() {
    int e = blockIdx.x * blockDim.x + threadIdx.x;
    if (e < EE) {
        int2 ed = g_edge[e];
        int p = atomicAdd(&g_cur[ed.y], 1);
        g_ssort[p] = ed.x;
    }
}

// Finalize norms from int histograms; rs0 = ns * w * x into buffer 0. (float4)
__global__ void k_init(const float* __restrict__ x) {
    int n = blockIdx.x * blockDim.x + threadIdx.x;
    if (n < NN / 4) {
        float w = g_scal[6];
        int4 cs = reinterpret_cast<const int4*>(g_cs)[n];
        int4 cd = reinterpret_cast<const int4*>(g_cd)[n];
        float4 xv = reinterpret_cast<const float4*>(x)[n];
        float4 ns, nd, rs;
        ns.x = rsqrtf(fmaxf((float)cs.x, 1.f)); nd.x = rsqrtf(fmaxf((float)cd.x, 1.f));
        ns.y = rsqrtf(fmaxf((float)cs.y, 1.f)); nd.y = rsqrtf(fmaxf((float)cd.y, 1.f));
        ns.z = rsqrtf(fmaxf((float)cs.z, 1.f)); nd.z = rsqrtf(fmaxf((float)cd.z, 1.f));
        ns.w = rsqrtf(fmaxf((float)cs.w, 1.f)); nd.w = rsqrtf(fmaxf((float)cd.w, 1.f));
        rs.x = ns.x * w * xv.x; rs.y = ns.y * w * xv.y;
        rs.z = ns.z * w * xv.z; rs.w = ns.w * w * xv.w;
        reinterpret_cast<float4*>(g_ns)[n] = ns;
        reinterpret_cast<float4*>(g_nd)[n] = nd;
        reinterpret_cast<float4*>(g_rs2[0])[n] = rs;
    }
}

// One full GraphConv hop, warp-per-node over CSR:
//   sum = Σ_{e in row(n)} rs_in[src[e]]   (contiguous edge run, random gathers)
//   rs_out[n] = ns[n] * (nd[n]*sum + s_k)   [k<5]
//   out[n]    = |nd[n]*sum + s5|            [k==5]
// No atomics, no separate post pass, no accumulator zeroing.
__global__ void k_hop(int k, float* __restrict__ out) {
    int n = (blockIdx.x * blockDim.x + threadIdx.x) >> 5;
    if (n >= NN) return;
    int lane = threadIdx.x & 31;
    const float* rin = g_rs2[k & 1];

    int start = g_row[n];
    int deg   = g_cd[n];
    float sum = 0.f;
    for (int j = lane; j < deg; j += 32)
        sum += __ldg(&rin[g_ssort[start + j]]);
#pragma unroll
    for (int off = 16; off > 0; off >>= 1)
        sum += __shfl_xor_sync(0xFFFFFFFFu, sum, off);

    if (lane == 0) {
        float v = g_nd[n] * sum + g_scal[k];
        if (k == 5) out[n] = fabsf(v);
        else        g_rs2[(k + 1) & 1][n] = g_ns[n] * v;
    }
}

extern "C" void kernel_launch(void* const* d_in, const int* in_sizes, int n_in,
                              void* d_out, int out_size) {
    // Layout A (dict order): x, src, dst, W0,b0..W5,b5
    // Layout B (sorted):     W0..W5, b0..b5, dst, src, x
    const float *x, *W0, *b0, *W1, *b1, *W2, *b2, *W3, *b3, *W4, *b4, *W5, *b5;
    const void *src, *dst;

    if (in_sizes[0] == NN) {
        x   = (const float*)d_in[0];
        src = d_in[1];
        dst = d_in[2];
        W0 = (const float*)d_in[3];  b0 = (const float*)d_in[4];
        W1 = (const float*)d_in[5];  b1 = (const float*)d_in[6];
        W2 = (const float*)d_in[7];  b2 = (const float*)d_in[8];
        W3 = (const float*)d_in[9];  b3 = (const float*)d_in[10];
        W4 = (const float*)d_in[11]; b4 = (const float*)d_in[12];
        W5 = (const float*)d_in[13]; b5 = (const float*)d_in[14];
    } else {
        W0 = (const float*)d_in[0];  W1 = (const float*)d_in[1];
        W2 = (const float*)d_in[2];  W3 = (const float*)d_in[3];
        W4 = (const float*)d_in[4];  W5 = (const float*)d_in[5];
        b0 = (const float*)d_in[6];  b1 = (const float*)d_in[7];
        b2 = (const float*)d_in[8];  b3 = (const float*)d_in[9];
        b4 = (const float*)d_in[10]; b5 = (const float*)d_in[11];
        dst = d_in[12];
        src = d_in[13];
        x   = (const float*)d_in[14];
    }
    float* out = (float*)d_out;

    const int TB = 256;
    const int GZ  = NPAD / 4 / TB + 2;            // setup: 98 zero blocks + 2
    const int GN4 = (NN / 4 + TB - 1) / TB;       // 98
    const int GE  = (EE + TB - 1) / TB;           // 6250
    const int GH  = (NN * 32 + TB - 1) / TB;      // warp-per-node hop: 12500

    k_setup<<<GZ, TB>>>((const unsigned long long*)src,
                        W0, b0, W1, b1, W2, b2, W3, b3, W4, b4, W5, b5);
    k_edges<<<GE, TB>>>(src, dst);
    k_scanA<<<98, TB>>>();
    k_scan3<<<98, TB>>>();
    k_perm<<<GE, TB>>>();
    k_init<<<GN4, TB>>>(x);

    for (int k = 0; k < 6; k++)
        k_hop<<<GH, TB>>>(k, out);
}

// round 9
// speedup vs baseline: 1.2392x; 1.2392x over previous
#include <cuda_runtime.h>

#define NN 100000
#define EE 1600000
#define NPAD (98 * 1024)          // NN padded to scan granularity (98 blocks x 1024)

// Static device scratch (allocation-free per harness rules)
__device__ float g_rs[NN];        // staged value ns*r_k (gathered in scatter)
__device__ float g_acc[NN];       // edge-scatter accumulator
__device__ float g_ns[NN];        // out_deg^-1/2
__device__ float g_nd[NN];        // in_deg^-1/2
__device__ int2  g_edge[EE];      // decoded (src,dst) in input order
__device__ __align__(16) int2 g_sort[EE];  // (src,dst) sorted by dst
__device__ int   g_cs[NPAD];      // src histogram (out-degree)
__device__ int   g_cd[NPAD];      // dst histogram (in-degree, sort key)
__device__ int   g_cur[NPAD];     // running offsets for permute
__device__ int   g_part[98];      // per-block partial sums
__device__ int   g_tick;          // monotone ticket counter (never reset)
__device__ float g_scal[8];       // s0..s5, w
__device__ int   g_is64;

// ---------------------------------------------------------------------------
// Fused setup: block 0 = collapse linear channel path to scalars; block 1 =
// index dtype probe (first 256 elems as u64: 2KB read, safe for either dtype;
// genuine int64 indices are all < NN, aliased int32 pairs exceed NN w.p. ~1);
// blocks 2.. = zero histograms + accumulator.
// ---------------------------------------------------------------------------
__global__ void k_setup(const unsigned long long* __restrict__ srcp,
                        const float* __restrict__ W0, const float* __restrict__ b0,
                        const float* __restrict__ W1, const float* __restrict__ b1,
                        const float* __restrict__ W2, const float* __restrict__ b2,
                        const float* __restrict__ W3, const float* __restrict__ b3,
                        const float* __restrict__ W4, const float* __restrict__ b4,
                        const float* __restrict__ W5, const float* __restrict__ b5) {
    int t = threadIdx.x;
    if (blockIdx.x == 0) {
        __shared__ float u5[32], u4[64], u3[128], u2[64], u1[32];
        if (t < 32) u5[t] = W5[t];
        __syncthreads();
        if (t < 64) { float s = 0.f; for (int j = 0; j < 32; j++) s += W4[t*32+j]*u5[j]; u4[t] = s; }
        __syncthreads();
        if (t < 128){ float s = 0.f; for (int j = 0; j < 64; j++) s += W3[t*64+j]*u4[j]; u3[t] = s; }
        __syncthreads();
        if (t < 64) { float s = 0.f; for (int j = 0; j < 128;j++) s += W2[t*128+j]*u3[j]; u2[t] = s; }
        __syncthreads();
        if (t < 32) { float s = 0.f; for (int j = 0; j < 64; j++) s += W1[t*64+j]*u2[j]; u1[t] = s; }
        __syncthreads();
        if (t == 0) {
            float w = 0.f, s0 = 0.f;
            for (int j = 0; j < 32; j++)  { w += W0[j]*u1[j]; s0 += b0[j]*u1[j]; }
            float s1 = 0.f; for (int j = 0; j < 64;  j++) s1 += b1[j]*u2[j];
            float s2 = 0.f; for (int j = 0; j < 128; j++) s2 += b2[j]*u3[j];
            float s3 = 0.f; for (int j = 0; j < 64;  j++) s3 += b3[j]*u4[j];
            float s4 = 0.f; for (int j = 0; j < 32;  j++) s4 += b4[j]*u5[j];
            g_scal[0]=s0; g_scal[1]=s1; g_scal[2]=s2; g_scal[3]=s3; g_scal[4]=s4;
            g_scal[5]=b5[0]; g_scal[6]=w;
        }
    } else if (blockIdx.x == 1) {
        int bad = (srcp[t] >= (unsigned long long)NN) ? 1 : 0;
        int any = __syncthreads_or(bad);
        if (t == 0) g_is64 = any ? 0 : 1;
    } else {
        int n = (blockIdx.x - 2) * blockDim.x + t;     // 0 .. NPAD/4-1
        if (n < NPAD / 4) {
            int4 zi = make_int4(0, 0, 0, 0);
            reinterpret_cast<int4*>(g_cs)[n] = zi;
            reinterpret_cast<int4*>(g_cd)[n] = zi;
            if (n < NN / 4)
                reinterpret_cast<float4*>(g_acc)[n] = make_float4(0.f, 0.f, 0.f, 0.f);
        }
    }
}

// Decode 1 edge/thread, clamp, store packed int2, build both histograms.
__global__ void k_edges(const void* __restrict__ srcv,
                        const void* __restrict__ dstv) {
    int e = blockIdx.x * blockDim.x + threadIdx.x;
    if (e < EE) {
        long long sl, dl;
        if (g_is64) {
            sl = ((const long long*)srcv)[e];
            dl = ((const long long*)dstv)[e];
        } else {
            sl = ((const int*)srcv)[e];
            dl = ((const int*)dstv)[e];
        }
        int s = (sl < 0) ? 0 : (sl >= NN ? NN - 1 : (int)sl);
        int d = (dl < 0) ? 0 : (dl >= NN ? NN - 1 : (int)dl);
        g_edge[e] = make_int2(s, d);
        atomicAdd(&g_cs[s], 1);
        atomicAdd(&g_cd[d], 1);
    }
}

// Fused full scan of g_cd -> g_cur (exclusive offsets). 98 co-resident blocks
// with an internal monotone ticket barrier: stage 1 per-block sums; barrier;
// each block computes its own base by masked reduce of g_part; stage 3 intra-
// block scan writes final offsets.
__global__ void k_scan() {
    int t = threadIdx.x, b = blockIdx.x;
    int4 c = reinterpret_cast<const int4*>(g_cd)[b * 256 + t];
    int tsum = c.x + c.y + c.z + c.w;

    __shared__ int sh[256];    // inclusive-scan workspace
    __shared__ int red[256];   // reduce workspace
    sh[t] = tsum;
    red[t] = tsum;
    __syncthreads();
    for (int off = 128; off > 0; off >>= 1) {
        if (t < off) red[t] += red[t + off];
        __syncthreads();
    }

    __shared__ int s_target;
    if (t == 0) {
        g_part[b] = red[0];
        __threadfence();
        int ticket = atomicAdd(&g_tick, 1);          // monotone across replays
        s_target = (ticket / 98 + 1) * 98;
        while ((*(volatile int*)&g_tick) - s_target < 0) { }
        __threadfence();
    }
    __syncthreads();

    // base_b = sum of g_part[j] for j < b  (volatile: other SMs wrote these)
    int pv = (t < b && t < 98) ? *(volatile int*)&g_part[t] : 0;
    red[t] = pv;
    __syncthreads();
    for (int off = 128; off > 0; off >>= 1) {
        if (t < off) red[t] += red[t + off];
        __syncthreads();
    }
    int base0 = red[0];

    // inclusive scan of tsum across the block
    for (int off = 1; off < 256; off <<= 1) {
        int a = (t >= off) ? sh[t - off] : 0;
        __syncthreads();
        sh[t] += a;
        __syncthreads();
    }
    int base = base0 + sh[t] - tsum;           // exclusive
    int4 o;
    o.x = base;
    o.y = o.x + c.x;
    o.z = o.y + c.y;
    o.w = o.z + c.z;
    reinterpret_cast<int4*>(g_cur)[b * 256 + t] = o;
}

// Fused permute + init. Blocks [0, GE): scatter edges into dst-sorted order
// (int2 random 8B writes). Blocks [GE, GE+98): finalize norms from histograms
// and stage rs0 = ns * w * x (independent of the permute).
__global__ void k_permInit(int ge, const float* __restrict__ x) {
    if (blockIdx.x < (unsigned)ge) {
        int e = blockIdx.x * blockDim.x + threadIdx.x;
        if (e < EE) {
            int2 ed = g_edge[e];
            int p = atomicAdd(&g_cur[ed.y], 1);
            g_sort[p] = ed;
        }
    } else {
        int n = (blockIdx.x - ge) * blockDim.x + threadIdx.x;
        if (n < NN / 4) {
            float w = g_scal[6];
            int4 cs = reinterpret_cast<const int4*>(g_cs)[n];
            int4 cd = reinterpret_cast<const int4*>(g_cd)[n];
            float4 xv = reinterpret_cast<const float4*>(x)[n];
            float4 ns, nd, rs;
            ns.x = rsqrtf(fmaxf((float)cs.x, 1.f)); nd.x = rsqrtf(fmaxf((float)cd.x, 1.f));
            ns.y = rsqrtf(fmaxf((float)cs.y, 1.f)); nd.y = rsqrtf(fmaxf((float)cd.y, 1.f));
            ns.z = rsqrtf(fmaxf((float)cs.z, 1.f)); nd.z = rsqrtf(fmaxf((float)cd.z, 1.f));
            ns.w = rsqrtf(fmaxf((float)cs.w, 1.f)); nd.w = rsqrtf(fmaxf((float)cd.w, 1.f));
            rs.x = ns.x * w * xv.x; rs.y = ns.y * w * xv.y;
            rs.z = ns.z * w * xv.z; rs.w = ns.w * w * xv.w;
            reinterpret_cast<float4*>(g_ns)[n] = ns;
            reinterpret_cast<float4*>(g_nd)[n] = nd;
            reinterpret_cast<float4*>(g_rs)[n] = rs;
        }
    }
}

// One propagation hop over dst-sorted edges: each thread serially accumulates
// 16 consecutive edges, flushing an atomic only on dst change (~2 atomics per
// thread since avg run length = 16). Edge reads: 128B contiguous per lane —
// every byte consumed. 16 independent gathers per thread (unrolled) for MLP.
__global__ void k_scatter16() {
    int i = blockIdx.x * blockDim.x + threadIdx.x;
    if (i >= EE / 16) return;
    const int4* p = reinterpret_cast<const int4*>(g_sort) + i * 8;  // 16 edges
    float run = 0.f;
    int cur = -1;
#pragma unroll
    for (int q = 0; q < 8; q++) {
        int4 v = p[q];                         // (s0,d0,s1,d1)
        float a0 = __ldg(&g_rs[v.x]);
        float a1 = __ldg(&g_rs[v.z]);
        if (v.y != cur) {
            if (cur >= 0) atomicAdd(&g_acc[cur], run);
            cur = v.y; run = 0.f;
        }
        run += a0;
        if (v.w != cur) {
            atomicAdd(&g_acc[cur], run);
            cur = v.w; run = 0.f;
        }
        run += a1;
    }
    atomicAdd(&g_acc[cur], run);
}

// r_{k+1} = nd*acc + s_k; stage rs = ns*r_{k+1}; re-zero acc. (float4)
__global__ void k_post(int k) {
    int n = blockIdx.x * blockDim.x + threadIdx.x;
    if (n < NN / 4) {
        float sk = g_scal[k];
        float4 nd = reinterpret_cast<float4*>(g_nd)[n];
        float4 ac = reinterpret_cast<float4*>(g_acc)[n];
        float4 ns = reinterpret_cast<float4*>(g_ns)[n];
        float4 rs;
        rs.x = ns.x * (nd.x * ac.x + sk);
        rs.y = ns.y * (nd.y * ac.y + sk);
        rs.z = ns.z * (nd.z * ac.z + sk);
        rs.w = ns.w * (nd.w * ac.w + sk);
        reinterpret_cast<float4*>(g_rs)[n] = rs;
        reinterpret_cast<float4*>(g_acc)[n] = make_float4(0.f, 0.f, 0.f, 0.f);
    }
}

// Final hop epilogue: out = |nd*acc + s5| (float4)
__global__ void k_final(float* __restrict__ out) {
    int n = blockIdx.x * blockDim.x + threadIdx.x;
    if (n < NN / 4) {
        float s5 = g_scal[5];
        float4 nd = reinterpret_cast<float4*>(g_nd)[n];
        float4 ac = reinterpret_cast<float4*>(g_acc)[n];
        float4 o;
        o.x = fabsf(nd.x * ac.x + s5);
        o.y = fabsf(nd.y * ac.y + s5);
        o.z = fabsf(nd.z * ac.z + s5);
        o.w = fabsf(nd.w * ac.w + s5);
        reinterpret_cast<float4*>(out)[n] = o;
    }
}

extern "C" void kernel_launch(void* const* d_in, const int* in_sizes, int n_in,
                              void* d_out, int out_size) {
    // Layout A (dict order): x, src, dst, W0,b0..W5,b5
    // Layout B (sorted):     W0..W5, b0..b5, dst, src, x
    const float *x, *W0, *b0, *W1, *b1, *W2, *b2, *W3, *b3, *W4, *b4, *W5, *b5;
    const void *src, *dst;

    if (in_sizes[0] == NN) {
        x   = (const float*)d_in[0];
        src = d_in[1];
        dst = d_in[2];
        W0 = (const float*)d_in[3];  b0 = (const float*)d_in[4];
        W1 = (const float*)d_in[5];  b1 = (const float*)d_in[6];
        W2 = (const float*)d_in[7];  b2 = (const float*)d_in[8];
        W3 = (const float*)d_in[9];  b3 = (const float*)d_in[10];
        W4 = (const float*)d_in[11]; b4 = (const float*)d_in[12];
        W5 = (const float*)d_in[13]; b5 = (const float*)d_in[14];
    } else {
        W0 = (const float*)d_in[0];  W1 = (const float*)d_in[1];
        W2 = (const float*)d_in[2];  W3 = (const float*)d_in[3];
        W4 = (const float*)d_in[4];  W5 = (const float*)d_in[5];
        b0 = (const float*)d_in[6];  b1 = (const float*)d_in[7];
        b2 = (const float*)d_in[8];  b3 = (const float*)d_in[9];
        b4 = (const float*)d_in[10]; b5 = (const float*)d_in[11];
        dst = d_in[12];
        src = d_in[13];
        x   = (const float*)d_in[14];
    }
    float* out = (float*)d_out;

    const int TB  = 256;
    const int GZ  = NPAD / 4 / TB + 2;            // setup: 98 zero blocks + 2
    const int GN4 = (NN / 4 + TB - 1) / TB;       // 98
    const int GE  = (EE + TB - 1) / TB;           // 6250
    const int GS  = (EE / 16 + TB - 1) / TB;      // 391

    k_setup<<<GZ, TB>>>((const unsigned long long*)src,
                        W0, b0, W1, b1, W2, b2, W3, b3, W4, b4, W5, b5);
    k_edges<<<GE, TB>>>(src, dst);
    k_scan<<<98, TB>>>();
    k_permInit<<<GE + GN4, TB>>>(GE, x);

    for (int k = 0; k < 5; k++) {
        k_scatter16<<<GS, TB>>>();
        k_post<<<GN4, TB>>>(k);
    }
    k_scatter16<<<GS, TB>>>();
    k_final<<<GN4, TB>>>(out);
}

// round 10
// speedup vs baseline: 1.3621x; 1.0991x over previous
#include <cuda_runtime.h>

#define NN 100000
#define EE 1600000
#define NPAD (98 * 1024)          // NN padded to scan granularity (98 blocks x 1024)

// Static device scratch (allocation-free per harness rules)
__device__ float g_rs[NN];        // staged value ns*r_k (gathered in scatter)
__device__ float g_acc[NN];       // edge-scatter accumulator
__device__ float g_ns[NN];        // out_deg^-1/2
__device__ float g_nd[NN];        // in_deg^-1/2
__device__ int2  g_edge[EE];      // decoded (src,dst) in input order
__device__ __align__(16) int2 g_sort[EE];  // (src,dst) sorted by dst
__device__ int   g_cs[NPAD];      // src histogram (out-degree)
__device__ int   g_cd[NPAD];      // dst histogram (in-degree, sort key)
__device__ int   g_cur[NPAD];     // running offsets for permute
__device__ int   g_part[98];      // per-block partial sums
__device__ int   g_tick;          // monotone ticket counter (never reset)
__device__ float g_scal[8];       // s0..s5, w
__device__ int   g_is64;

// ---------------------------------------------------------------------------
// Fused setup: block 0 = collapse linear channel path to scalars; block 1 =
// index dtype probe (first 256 elems as u64: 2KB read, safe for either dtype;
// genuine int64 indices are all < NN, aliased int32 pairs exceed NN w.p. ~1);
// blocks 2.. = zero histograms + accumulator.
// ---------------------------------------------------------------------------
__global__ void k_setup(const unsigned long long* __restrict__ srcp,
                        const float* __restrict__ W0, const float* __restrict__ b0,
                        const float* __restrict__ W1, const float* __restrict__ b1,
                        const float* __restrict__ W2, const float* __restrict__ b2,
                        const float* __restrict__ W3, const float* __restrict__ b3,
                        const float* __restrict__ W4, const float* __restrict__ b4,
                        const float* __restrict__ W5, const float* __restrict__ b5) {
    int t = threadIdx.x;
    if (blockIdx.x == 0) {
        __shared__ float u5[32], u4[64], u3[128], u2[64], u1[32];
        if (t < 32) u5[t] = W5[t];
        __syncthreads();
        if (t < 64) { float s = 0.f; for (int j = 0; j < 32; j++) s += W4[t*32+j]*u5[j]; u4[t] = s; }
        __syncthreads();
        if (t < 128){ float s = 0.f; for (int j = 0; j < 64; j++) s += W3[t*64+j]*u4[j]; u3[t] = s; }
        __syncthreads();
        if (t < 64) { float s = 0.f; for (int j = 0; j < 128;j++) s += W2[t*128+j]*u3[j]; u2[t] = s; }
        __syncthreads();
        if (t < 32) { float s = 0.f; for (int j = 0; j < 64; j++) s += W1[t*64+j]*u2[j]; u1[t] = s; }
        __syncthreads();
        if (t == 0) {
            float w = 0.f, s0 = 0.f;
            for (int j = 0; j < 32; j++)  { w += W0[j]*u1[j]; s0 += b0[j]*u1[j]; }
            float s1 = 0.f; for (int j = 0; j < 64;  j++) s1 += b1[j]*u2[j];
            float s2 = 0.f; for (int j = 0; j < 128; j++) s2 += b2[j]*u3[j];
            float s3 = 0.f; for (int j = 0; j < 64;  j++) s3 += b3[j]*u4[j];
            float s4 = 0.f; for (int j = 0; j < 32;  j++) s4 += b4[j]*u5[j];
            g_scal[0]=s0; g_scal[1]=s1; g_scal[2]=s2; g_scal[3]=s3; g_scal[4]=s4;
            g_scal[5]=b5[0]; g_scal[6]=w;
        }
    } else if (blockIdx.x == 1) {
        int bad = (srcp[t] >= (unsigned long long)NN) ? 1 : 0;
        int any = __syncthreads_or(bad);
        if (t == 0) g_is64 = any ? 0 : 1;
    } else {
        int n = (blockIdx.x - 2) * blockDim.x + t;     // 0 .. NPAD/4-1
        if (n < NPAD / 4) {
            int4 zi = make_int4(0, 0, 0, 0);
            reinterpret_cast<int4*>(g_cs)[n] = zi;
            reinterpret_cast<int4*>(g_cd)[n] = zi;
            if (n < NN / 4)
                reinterpret_cast<float4*>(g_acc)[n] = make_float4(0.f, 0.f, 0.f, 0.f);
        }
    }
}

// Decode 1 edge/thread, clamp, store packed int2, build both histograms.
__global__ void k_edges(const void* __restrict__ srcv,
                        const void* __restrict__ dstv) {
    int e = blockIdx.x * blockDim.x + threadIdx.x;
    if (e < EE) {
        long long sl, dl;
        if (g_is64) {
            sl = ((const long long*)srcv)[e];
            dl = ((const long long*)dstv)[e];
        } else {
            sl = ((const int*)srcv)[e];
            dl = ((const int*)dstv)[e];
        }
        int s = (sl < 0) ? 0 : (sl >= NN ? NN - 1 : (int)sl);
        int d = (dl < 0) ? 0 : (dl >= NN ? NN - 1 : (int)dl);
        g_edge[e] = make_int2(s, d);
        atomicAdd(&g_cs[s], 1);
        atomicAdd(&g_cd[d], 1);
    }
}

// Fused full scan of g_cd -> g_cur (exclusive offsets). 98 co-resident blocks
// with an internal monotone ticket barrier.
__global__ void k_scan() {
    int t = threadIdx.x, b = blockIdx.x;
    int4 c = reinterpret_cast<const int4*>(g_cd)[b * 256 + t];
    int tsum = c.x + c.y + c.z + c.w;

    __shared__ int sh[256];    // inclusive-scan workspace
    __shared__ int red[256];   // reduce workspace
    sh[t] = tsum;
    red[t] = tsum;
    __syncthreads();
    for (int off = 128; off > 0; off >>= 1) {
        if (t < off) red[t] += red[t + off];
        __syncthreads();
    }

    __shared__ int s_target;
    if (t == 0) {
        g_part[b] = red[0];
        __threadfence();
        int ticket = atomicAdd(&g_tick, 1);          // monotone across replays
        s_target = (ticket / 98 + 1) * 98;
        while ((*(volatile int*)&g_tick) - s_target < 0) { }
        __threadfence();
    }
    __syncthreads();

    // base_b = sum of g_part[j] for j < b  (volatile: other SMs wrote these)
    int pv = (t < b && t < 98) ? *(volatile int*)&g_part[t] : 0;
    red[t] = pv;
    __syncthreads();
    for (int off = 128; off > 0; off >>= 1) {
        if (t < off) red[t] += red[t + off];
        __syncthreads();
    }
    int base0 = red[0];

    // inclusive scan of tsum across the block
    for (int off = 1; off < 256; off <<= 1) {
        int a = (t >= off) ? sh[t - off] : 0;
        __syncthreads();
        sh[t] += a;
        __syncthreads();
    }
    int base = base0 + sh[t] - tsum;           // exclusive
    int4 o;
    o.x = base;
    o.y = o.x + c.x;
    o.z = o.y + c.y;
    o.w = o.z + c.z;
    reinterpret_cast<int4*>(g_cur)[b * 256 + t] = o;
}

// Fused permute + init. Blocks [0, GE): scatter edges into dst-sorted order.
// Blocks [GE, GE+98): finalize norms and stage rs0 = ns * w * x.
__global__ void k_permInit(int ge, const float* __restrict__ x) {
    if (blockIdx.x < (unsigned)ge) {
        int e = blockIdx.x * blockDim.x + threadIdx.x;
        if (e < EE) {
            int2 ed = g_edge[e];
            int p = atomicAdd(&g_cur[ed.y], 1);
            g_sort[p] = ed;
        }
    } else {
        int n = (blockIdx.x - ge) * blockDim.x + threadIdx.x;
        if (n < NN / 4) {
            float w = g_scal[6];
            int4 cs = reinterpret_cast<const int4*>(g_cs)[n];
            int4 cd = reinterpret_cast<const int4*>(g_cd)[n];
            float4 xv = reinterpret_cast<const float4*>(x)[n];
            float4 ns, nd, rs;
            ns.x = rsqrtf(fmaxf((float)cs.x, 1.f)); nd.x = rsqrtf(fmaxf((float)cd.x, 1.f));
            ns.y = rsqrtf(fmaxf((float)cs.y, 1.f)); nd.y = rsqrtf(fmaxf((float)cd.y, 1.f));
            ns.z = rsqrtf(fmaxf((float)cs.z, 1.f)); nd.z = rsqrtf(fmaxf((float)cd.z, 1.f));
            ns.w = rsqrtf(fmaxf((float)cs.w, 1.f)); nd.w = rsqrtf(fmaxf((float)cd.w, 1.f));
            rs.x = ns.x * w * xv.x; rs.y = ns.y * w * xv.y;
            rs.z = ns.z * w * xv.z; rs.w = ns.w * w * xv.w;
            reinterpret_cast<float4*>(g_ns)[n] = ns;
            reinterpret_cast<float4*>(g_nd)[n] = nd;
            reinterpret_cast<float4*>(g_rs)[n] = rs;
        }
    }
}

// One propagation hop over dst-sorted edges with warp-segmented reduction
// (R7-proven): contiguous equal-dst runs summed in-warp via shfl; only run
// tails issue atomicAdd (~100K instead of 1.6M).
__global__ void k_scatter() {
    int e = blockIdx.x * blockDim.x + threadIdx.x;
    if (e >= EE) return;
    int2 ed = g_sort[e];
    float v = __ldg(&g_rs[ed.x]);
    int d = ed.y;
    unsigned lane = threadIdx.x & 31;

    int dprev = __shfl_up_sync(0xFFFFFFFFu, d, 1);
    bool head = (lane == 0) || (d != dprev);
    unsigned hm = __ballot_sync(0xFFFFFFFFu, head);
    unsigned below = hm & ((2u << lane) - 1u);
    int start = 31 - __clz(below);

#pragma unroll
    for (int off = 1; off < 32; off <<= 1) {
        float u = __shfl_up_sync(0xFFFFFFFFu, v, off);
        if ((int)lane - off >= start) v += u;
    }
    bool tail = (lane == 31) || ((hm >> (lane + 1)) & 1u);
    if (tail) atomicAdd(&g_acc[d], v);
}

// r_{k+1} = nd*acc + s_k. k<5: stage rs = ns*r_{k+1}, re-zero acc.
// k==5: out = |r_6|. (float4)
__global__ void k_post(int k, float* __restrict__ out) {
    int n = blockIdx.x * blockDim.x + threadIdx.x;
    if (n < NN / 4) {
        float sk = g_scal[k];
        float4 nd = reinterpret_cast<float4*>(g_nd)[n];
        float4 ac = reinterpret_cast<float4*>(g_acc)[n];
        float4 v;
        v.x = nd.x * ac.x + sk;
        v.y = nd.y * ac.y + sk;
        v.z = nd.z * ac.z + sk;
        v.w = nd.w * ac.w + sk;
        if (k == 5) {
            float4 o;
            o.x = fabsf(v.x); o.y = fabsf(v.y);
            o.z = fabsf(v.z); o.w = fabsf(v.w);
            reinterpret_cast<float4*>(out)[n] = o;
        } else {
            float4 ns = reinterpret_cast<float4*>(g_ns)[n];
            float4 rs;
            rs.x = ns.x * v.x; rs.y = ns.y * v.y;
            rs.z = ns.z * v.z; rs.w = ns.w * v.w;
            reinterpret_cast<float4*>(g_rs)[n] = rs;
            reinterpret_cast<float4*>(g_acc)[n] = make_float4(0.f, 0.f, 0.f, 0.f);
        }
    }
}

extern "C" void kernel_launch(void* const* d_in, const int* in_sizes, int n_in,
                              void* d_out, int out_size) {
    // Layout A (dict order): x, src, dst, W0,b0..W5,b5
    // Layout B (sorted):     W0..W5, b0..b5, dst, src, x
    const float *x, *W0, *b0, *W1, *b1, *W2, *b2, *W3, *b3, *W4, *b4, *W5, *b5;
    const void *src, *dst;

    if (in_sizes[0] == NN) {
        x   = (const float*)d_in[0];
        src = d_in[1];
        dst = d_in[2];
        W0 = (const float*)d_in[3];  b0 = (const float*)d_in[4];
        W1 = (const float*)d_in[5];  b1 = (const float*)d_in[6];
        W2 = (const float*)d_in[7];  b2 = (const float*)d_in[8];
        W3 = (const float*)d_in[9];  b3 = (const float*)d_in[10];
        W4 = (const float*)d_in[11]; b4 = (const float*)d_in[12];
        W5 = (const float*)d_in[13]; b5 = (const float*)d_in[14];
    } else {
        W0 = (const float*)d_in[0];  W1 = (const float*)d_in[1];
        W2 = (const float*)d_in[2];  W3 = (const float*)d_in[3];
        W4 = (const float*)d_in[4];  W5 = (const float*)d_in[5];
        b0 = (const float*)d_in[6];  b1 = (const float*)d_in[7];
        b2 = (const float*)d_in[8];  b3 = (const float*)d_in[9];
        b4 = (const float*)d_in[10]; b5 = (const float*)d_in[11];
        dst = d_in[12];
        src = d_in[13];
        x   = (const float*)d_in[14];
    }
    float* out = (float*)d_out;

    const int TB  = 256;
    const int GZ  = NPAD / 4 / TB + 2;            // setup: 98 zero blocks + 2
    const int GN4 = (NN / 4 + TB - 1) / TB;       // 98
    const int GE  = (EE + TB - 1) / TB;           // 6250

    k_setup<<<GZ, TB>>>((const unsigned long long*)src,
                        W0, b0, W1, b1, W2, b2, W3, b3, W4, b4, W5, b5);
    k_edges<<<GE, TB>>>(src, dst);
    k_scan<<<98, TB>>>();
    k_permInit<<<GE + GN4, TB>>>(GE, x);

    for (int k = 0; k < 6; k++) {
        k_scatter<<<GE, TB>>>();
        k_post<<<GN4, TB>>>(k, out);
    }
}

// round 11
// speedup vs baseline: 1.3854x; 1.0171x over previous
#include <cuda_runtime.h>

#define NN 100000
#define EE 1600000
#define NPAD (98 * 1024)          // NN padded to scan granularity (98 blocks x 1024)

// Static device scratch (allocation-free per harness rules)
__device__ float g_rs[NN];        // staged value ns*r_k (gathered in scatter)
__device__ float g_acc[NN];       // edge-scatter accumulator
__device__ float g_ns[NN];        // out_deg^-1/2
__device__ float g_nd[NN];        // in_deg^-1/2
__device__ int2  g_edge[EE];      // (src, dst | rank<<17) in input order
__device__ __align__(16) int2 g_sort[EE];  // (src, dst) sorted by dst
__device__ int   g_cs[NPAD];      // src histogram (out-degree)
__device__ int   g_cd[NPAD];      // dst histogram (in-degree, sort key)
__device__ int   g_row[NPAD];     // exclusive scan of g_cd (CSR row starts)
__device__ int   g_part[98];      // per-block partial sums
__device__ int   g_tick;          // monotone ticket counter (never reset)
__device__ float g_scal[8];       // s0..s5, w
__device__ int   g_is64;

#define DMASK 0x1FFFF             // low 17 bits: dst  (NN=100000 < 2^17)

// ---------------------------------------------------------------------------
// Fused setup: block 0 = collapse linear channel path to scalars; block 1 =
// index dtype probe (first 256 elems as u64: 2KB read, safe for either dtype;
// genuine int64 indices are all < NN, aliased int32 pairs exceed NN w.p. ~1);
// blocks 2.. = zero histograms + accumulator.
// ---------------------------------------------------------------------------
__global__ void k_setup(const unsigned long long* __restrict__ srcp,
                        const float* __restrict__ W0, const float* __restrict__ b0,
                        const float* __restrict__ W1, const float* __restrict__ b1,
                        const float* __restrict__ W2, const float* __restrict__ b2,
                        const float* __restrict__ W3, const float* __restrict__ b3,
                        const float* __restrict__ W4, const float* __restrict__ b4,
                        const float* __restrict__ W5, const float* __restrict__ b5) {
    int t = threadIdx.x;
    if (blockIdx.x == 0) {
        __shared__ float u5[32], u4[64], u3[128], u2[64], u1[32];
        if (t < 32) u5[t] = W5[t];
        __syncthreads();
        if (t < 64) { float s = 0.f; for (int j = 0; j < 32; j++) s += W4[t*32+j]*u5[j]; u4[t] = s; }
        __syncthreads();
        if (t < 128){ float s = 0.f; for (int j = 0; j < 64; j++) s += W3[t*64+j]*u4[j]; u3[t] = s; }
        __syncthreads();
        if (t < 64) { float s = 0.f; for (int j = 0; j < 128;j++) s += W2[t*128+j]*u3[j]; u2[t] = s; }
        __syncthreads();
        if (t < 32) { float s = 0.f; for (int j = 0; j < 64; j++) s += W1[t*64+j]*u2[j]; u1[t] = s; }
        __syncthreads();
        if (t == 0) {
            float w = 0.f, s0 = 0.f;
            for (int j = 0; j < 32; j++)  { w += W0[j]*u1[j]; s0 += b0[j]*u1[j]; }
            float s1 = 0.f; for (int j = 0; j < 64;  j++) s1 += b1[j]*u2[j];
            float s2 = 0.f; for (int j = 0; j < 128; j++) s2 += b2[j]*u3[j];
            float s3 = 0.f; for (int j = 0; j < 64;  j++) s3 += b3[j]*u4[j];
            float s4 = 0.f; for (int j = 0; j < 32;  j++) s4 += b4[j]*u5[j];
            g_scal[0]=s0; g_scal[1]=s1; g_scal[2]=s2; g_scal[3]=s3; g_scal[4]=s4;
            g_scal[5]=b5[0]; g_scal[6]=w;
        }
    } else if (blockIdx.x == 1) {
        int bad = (srcp[t] >= (unsigned long long)NN) ? 1 : 0;
        int any = __syncthreads_or(bad);
        if (t == 0) g_is64 = any ? 0 : 1;
    } else {
        int n = (blockIdx.x - 2) * blockDim.x + t;     // 0 .. NPAD/4-1
        if (n < NPAD / 4) {
            int4 zi = make_int4(0, 0, 0, 0);
            reinterpret_cast<int4*>(g_cs)[n] = zi;
            reinterpret_cast<int4*>(g_cd)[n] = zi;
            if (n < NN / 4)
                reinterpret_cast<float4*>(g_acc)[n] = make_float4(0.f, 0.f, 0.f, 0.f);
        }
    }
}

// Decode 1 edge/thread, clamp, histogram both endpoints. The dst atomic's
// RETURN VALUE is the edge's rank within its bucket — pack it into the high
// 15 bits next to dst so the permute needs no atomics at all.
__global__ void k_edges(const void* __restrict__ srcv,
                        const void* __restrict__ dstv) {
    int e = blockIdx.x * blockDim.x + threadIdx.x;
    if (e < EE) {
        long long sl, dl;
        if (g_is64) {
            sl = ((const long long*)srcv)[e];
            dl = ((const long long*)dstv)[e];
        } else {
            sl = ((const int*)srcv)[e];
            dl = ((const int*)dstv)[e];
        }
        int s = (sl < 0) ? 0 : (sl >= NN ? NN - 1 : (int)sl);
        int d = (dl < 0) ? 0 : (dl >= NN ? NN - 1 : (int)dl);
        atomicAdd(&g_cs[s], 1);
        int r = atomicAdd(&g_cd[d], 1);        // rank within dst bucket
        g_edge[e] = make_int2(s, d | (r << 17));
    }
}

// Fused full scan of g_cd -> g_row (exclusive offsets). 98 co-resident blocks
// with an internal monotone ticket barrier.
__global__ void k_scan() {
    int t = threadIdx.x, b = blockIdx.x;
    int4 c = reinterpret_cast<const int4*>(g_cd)[b * 256 + t];
    int tsum = c.x + c.y + c.z + c.w;

    __shared__ int sh[256];    // inclusive-scan workspace
    __shared__ int red[256];   // reduce workspace
    sh[t] = tsum;
    red[t] = tsum;
    __syncthreads();
    for (int off = 128; off > 0; off >>= 1) {
        if (t < off) red[t] += red[t + off];
        __syncthreads();
    }

    __shared__ int s_target;
    if (t == 0) {
        g_part[b] = red[0];
        __threadfence();
        int ticket = atomicAdd(&g_tick, 1);          // monotone across replays
        s_target = (ticket / 98 + 1) * 98;
        while ((*(volatile int*)&g_tick) - s_target < 0) { }
        __threadfence();
    }
    __syncthreads();

    // base_b = sum of g_part[j] for j < b  (volatile: other SMs wrote these)
    int pv = (t < b && t < 98) ? *(volatile int*)&g_part[t] : 0;
    red[t] = pv;
    __syncthreads();
    for (int off = 128; off > 0; off >>= 1) {
        if (t < off) red[t] += red[t + off];
        __syncthreads();
    }
    int base0 = red[0];

    // inclusive scan of tsum across the block
    for (int off = 1; off < 256; off <<= 1) {
        int a = (t >= off) ? sh[t - off] : 0;
        __syncthreads();
        sh[t] += a;
        __syncthreads();
    }
    int base = base0 + sh[t] - tsum;           // exclusive
    int4 o;
    o.x = base;
    o.y = o.x + c.x;
    o.z = o.y + c.y;
    o.w = o.z + c.z;
    reinterpret_cast<int4*>(g_row)[b * 256 + t] = o;
}

// Fused permute + init. Blocks [0, GE): place each edge at row[dst]+rank
// (NO atomics — rank precomputed in k_edges). Blocks [GE, GE+98): finalize
// norms and stage rs0 = ns * w * x.
__global__ void k_permInit(int ge, const float* __restrict__ x) {
    if (blockIdx.x < (unsigned)ge) {
        int e = blockIdx.x * blockDim.x + threadIdx.x;
        if (e < EE) {
            int2 ed = g_edge[e];
            int d = ed.y & DMASK;
            int r = ((unsigned)ed.y) >> 17;
            g_sort[g_row[d] + r] = make_int2(ed.x, d);
        }
    } else {
        int n = (blockIdx.x - ge) * blockDim.x + threadIdx.x;
        if (n < NN / 4) {
            float w = g_scal[6];
            int4 cs = reinterpret_cast<const int4*>(g_cs)[n];
            int4 cd = reinterpret_cast<const int4*>(g_cd)[n];
            float4 xv = reinterpret_cast<const float4*>(x)[n];
            float4 ns, nd, rs;
            ns.x = rsqrtf(fmaxf((float)cs.x, 1.f)); nd.x = rsqrtf(fmaxf((float)cd.x, 1.f));
            ns.y = rsqrtf(fmaxf((float)cs.y, 1.f)); nd.y = rsqrtf(fmaxf((float)cd.y, 1.f));
            ns.z = rsqrtf(fmaxf((float)cs.z, 1.f)); nd.z = rsqrtf(fmaxf((float)cd.z, 1.f));
            ns.w = rsqrtf(fmaxf((float)cs.w, 1.f)); nd.w = rsqrtf(fmaxf((float)cd.w, 1.f));
            rs.x = ns.x * w * xv.x; rs.y = ns.y * w * xv.y;
            rs.z = ns.z * w * xv.z; rs.w = ns.w * w * xv.w;
            reinterpret_cast<float4*>(g_ns)[n] = ns;
            reinterpret_cast<float4*>(g_nd)[n] = nd;
            reinterpret_cast<float4*>(g_rs)[n] = rs;
        }
    }
}

// One propagation hop over dst-sorted edges with warp-segmented reduction:
// contiguous equal-dst runs summed in-warp via shfl; only run tails issue
// atomicAdd (~100K instead of 1.6M).
__global__ void k_scatter() {
    int e = blockIdx.x * blockDim.x + threadIdx.x;
    if (e >= EE) return;
    int2 ed = g_sort[e];
    float v = __ldg(&g_rs[ed.x]);
    int d = ed.y;
    unsigned lane = threadIdx.x & 31;

    int dprev = __shfl_up_sync(0xFFFFFFFFu, d, 1);
    bool head = (lane == 0) || (d != dprev);
    unsigned hm = __ballot_sync(0xFFFFFFFFu, head);
    unsigned below = hm & ((2u << lane) - 1u);
    int start = 31 - __clz(below);

#pragma unroll
    for (int off = 1; off < 32; off <<= 1) {
        float u = __shfl_up_sync(0xFFFFFFFFu, v, off);
        if ((int)lane - off >= start) v += u;
    }
    bool tail = (lane == 31) || ((hm >> (lane + 1)) & 1u);
    if (tail) atomicAdd(&g_acc[d], v);
}

// r_{k+1} = nd*acc + s_k. k<5: stage rs = ns*r_{k+1}, re-zero acc.
// k==5: out = |r_6|. (float4)
__global__ void k_post(int k, float* __restrict__ out) {
    int n = blockIdx.x * blockDim.x + threadIdx.x;
    if (n < NN / 4) {
        float sk = g_scal[k];
        float4 nd = reinterpret_cast<float4*>(g_nd)[n];
        float4 ac = reinterpret_cast<float4*>(g_acc)[n];
        float4 v;
        v.x = nd.x * ac.x + sk;
        v.y = nd.y * ac.y + sk;
        v.z = nd.z * ac.z + sk;
        v.w = nd.w * ac.w + sk;
        if (k == 5) {
            float4 o;
            o.x = fabsf(v.x); o.y = fabsf(v.y);
            o.z = fabsf(v.z); o.w = fabsf(v.w);
            reinterpret_cast<float4*>(out)[n] = o;
        } else {
            float4 ns = reinterpret_cast<float4*>(g_ns)[n];
            float4 rs;
            rs.x = ns.x * v.x; rs.y = ns.y * v.y;
            rs.z = ns.z * v.z; rs.w = ns.w * v.w;
            reinterpret_cast<float4*>(g_rs)[n] = rs;
            reinterpret_cast<float4*>(g_acc)[n] = make_float4(0.f, 0.f, 0.f, 0.f);
        }
    }
}

extern "C" void kernel_launch(void* const* d_in, const int* in_sizes, int n_in,
                              void* d_out, int out_size) {
    // Layout A (dict order): x, src, dst, W0,b0..W5,b5
    // Layout B (sorted):     W0..W5, b0..b5, dst, src, x
    const float *x, *W0, *b0, *W1, *b1, *W2, *b2, *W3, *b3, *W4, *b4, *W5, *b5;
    const void *src, *dst;

    if (in_sizes[0] == NN) {
        x   = (const float*)d_in[0];
        src = d_in[1];
        dst = d_in[2];
        W0 = (const float*)d_in[3];  b0 = (const float*)d_in[4];
        W1 = (const float*)d_in[5];  b1 = (const float*)d_in[6];
        W2 = (const float*)d_in[7];  b2 = (const float*)d_in[8];
        W3 = (const float*)d_in[9];  b3 = (const float*)d_in[10];
        W4 = (const float*)d_in[11]; b4 = (const float*)d_in[12];
        W5 = (const float*)d_in[13]; b5 = (const float*)d_in[14];
    } else {
        W0 = (const float*)d_in[0];  W1 = (const float*)d_in[1];
        W2 = (const float*)d_in[2];  W3 = (const float*)d_in[3];
        W4 = (const float*)d_in[4];  W5 = (const float*)d_in[5];
        b0 = (const float*)d_in[6];  b1 = (const float*)d_in[7];
        b2 = (const float*)d_in[8];  b3 = (const float*)d_in[9];
        b4 = (const float*)d_in[10]; b5 = (const float*)d_in[11];
        dst = d_in[12];
        src = d_in[13];
        x   = (const float*)d_in[14];
    }
    float* out = (float*)d_out;

    const int TB  = 256;
    const int GZ  = NPAD / 4 / TB + 2;            // setup: 98 zero blocks + 2
    const int GN4 = (NN / 4 + TB - 1) / TB;       // 98
    const int GE  = (EE + TB - 1) / TB;           // 6250

    k_setup<<<GZ, TB>>>((const unsigned long long*)src,
                        W0, b0, W1, b1, W2, b2, W3, b3, W4, b4, W5, b5);
    k_edges<<<GE, TB>>>(src, dst);
    k_scan<<<98, TB>>>();
    k_permInit<<<GE + GN4, TB>>>(GE, x);

    for (int k = 0; k < 6; k++) {
        k_scatter<<<GE, TB>>>();
        k_post<<<GN4, TB>>>(k, out);
    }
}

// round 12
// speedup vs baseline: 1.4507x; 1.0471x over previous
#include <cuda_runtime.h>

#define NN 100000
#define EE 1600000
#define NPAD (98 * 1024)          // NN padded to scan granularity (98 blocks x 1024)

// Static device scratch (allocation-free per harness rules)
__device__ float g_rs[NN];        // staged value ns*r_k (gathered in scatter)
__device__ float g_acc[NN];       // edge-scatter accumulator
__device__ float g_ns[NN];        // out_deg^-1/2
__device__ float g_nd[NN];        // in_deg^-1/2
__device__ int2  g_edge[EE];      // (src, dst | rank<<17) in input order
__device__ __align__(16) int2 g_sort[EE];  // (src, dst) sorted by dst
__device__ int   g_cs[NPAD];      // src histogram (out-degree)
__device__ int   g_cd[NPAD];      // dst histogram (in-degree, sort key)
__device__ int   g_row[NPAD];     // exclusive scan of g_cd (CSR row starts)
__device__ int   g_part[98];      // per-block partial sums
__device__ int   g_tick;          // monotone ticket counter (never reset)
__device__ float g_scal[8];       // s0..s5, w
__device__ int   g_is64;

#define DMASK 0x1FFFF             // low 17 bits: dst  (NN=100000 < 2^17)

// ---------------------------------------------------------------------------
// Fused setup: block 0 = collapse linear channel path to scalars; block 1 =
// index dtype probe (first 256 elems as u64: 2KB read, safe for either dtype;
// genuine int64 indices are all < NN, aliased int32 pairs exceed NN w.p. ~1);
// blocks 2.. = zero histograms + accumulator.
// ---------------------------------------------------------------------------
__global__ void k_setup(const unsigned long long* __restrict__ srcp,
                        const float* __restrict__ W0, const float* __restrict__ b0,
                        const float* __restrict__ W1, const float* __restrict__ b1,
                        const float* __restrict__ W2, const float* __restrict__ b2,
                        const float* __restrict__ W3, const float* __restrict__ b3,
                        const float* __restrict__ W4, const float* __restrict__ b4,
                        const float* __restrict__ W5, const float* __restrict__ b5) {
    int t = threadIdx.x;
    if (blockIdx.x == 0) {
        __shared__ float u5[32], u4[64], u3[128], u2[64], u1[32];
        if (t < 32) u5[t] = W5[t];
        __syncthreads();
        if (t < 64) { float s = 0.f; for (int j = 0; j < 32; j++) s += W4[t*32+j]*u5[j]; u4[t] = s; }
        __syncthreads();
        if (t < 128){ float s = 0.f; for (int j = 0; j < 64; j++) s += W3[t*64+j]*u4[j]; u3[t] = s; }
        __syncthreads();
        if (t < 64) { float s = 0.f; for (int j = 0; j < 128;j++) s += W2[t*128+j]*u3[j]; u2[t] = s; }
        __syncthreads();
        if (t < 32) { float s = 0.f; for (int j = 0; j < 64; j++) s += W1[t*64+j]*u2[j]; u1[t] = s; }
        __syncthreads();
        if (t == 0) {
            float w = 0.f, s0 = 0.f;
            for (int j = 0; j < 32; j++)  { w += W0[j]*u1[j]; s0 += b0[j]*u1[j]; }
            float s1 = 0.f; for (int j = 0; j < 64;  j++) s1 += b1[j]*u2[j];
            float s2 = 0.f; for (int j = 0; j < 128; j++) s2 += b2[j]*u3[j];
            float s3 = 0.f; for (int j = 0; j < 64;  j++) s3 += b3[j]*u4[j];
            float s4 = 0.f; for (int j = 0; j < 32;  j++) s4 += b4[j]*u5[j];
            g_scal[0]=s0; g_scal[1]=s1; g_scal[2]=s2; g_scal[3]=s3; g_scal[4]=s4;
            g_scal[5]=b5[0]; g_scal[6]=w;
        }
    } else if (blockIdx.x == 1) {
        int bad = (srcp[t] >= (unsigned long long)NN) ? 1 : 0;
        int any = __syncthreads_or(bad);
        if (t == 0) g_is64 = any ? 0 : 1;
    } else {
        int n = (blockIdx.x - 2) * blockDim.x + t;     // 0 .. NPAD/4-1
        if (n < NPAD / 4) {
            int4 zi = make_int4(0, 0, 0, 0);
            reinterpret_cast<int4*>(g_cs)[n] = zi;
            reinterpret_cast<int4*>(g_cd)[n] = zi;
            if (n < NN / 4)
                reinterpret_cast<float4*>(g_acc)[n] = make_float4(0.f, 0.f, 0.f, 0.f);
        }
    }
}

// Decode 1 edge/thread, clamp, histogram both endpoints. The dst atomic's
// RETURN VALUE is the edge's rank within its bucket — packed into the high
// bits next to dst so the permute needs no atomics.
__global__ void k_edges(const void* __restrict__ srcv,
                        const void* __restrict__ dstv) {
    int e = blockIdx.x * blockDim.x + threadIdx.x;
    if (e < EE) {
        long long sl, dl;
        if (g_is64) {
            sl = ((const long long*)srcv)[e];
            dl = ((const long long*)dstv)[e];
        } else {
            sl = ((const int*)srcv)[e];
            dl = ((const int*)dstv)[e];
        }
        int s = (sl < 0) ? 0 : (sl >= NN ? NN - 1 : (int)sl);
        int d = (dl < 0) ? 0 : (dl >= NN ? NN - 1 : (int)dl);
        atomicAdd(&g_cs[s], 1);
        int r = atomicAdd(&g_cd[d], 1);        // rank within dst bucket
        g_edge[e] = make_int2(s, d | (r << 17));
    }
}

// Fused full scan of g_cd -> g_row (exclusive offsets). 98 co-resident blocks
// with an internal monotone ticket barrier.
__global__ void k_scan() {
    int t = threadIdx.x, b = blockIdx.x;
    int4 c = reinterpret_cast<const int4*>(g_cd)[b * 256 + t];
    int tsum = c.x + c.y + c.z + c.w;

    __shared__ int sh[256];    // inclusive-scan workspace
    __shared__ int red[256];   // reduce workspace
    sh[t] = tsum;
    red[t] = tsum;
    __syncthreads();
    for (int off = 128; off > 0; off >>= 1) {
        if (t < off) red[t] += red[t + off];
        __syncthreads();
    }

    __shared__ int s_target;
    if (t == 0) {
        g_part[b] = red[0];
        __threadfence();
        int ticket = atomicAdd(&g_tick, 1);          // monotone across replays
        s_target = (ticket / 98 + 1) * 98;
        while ((*(volatile int*)&g_tick) - s_target < 0) { }
        __threadfence();
    }
    __syncthreads();

    // base_b = sum of g_part[j] for j < b  (volatile: other SMs wrote these)
    int pv = (t < b && t < 98) ? *(volatile int*)&g_part[t] : 0;
    red[t] = pv;
    __syncthreads();
    for (int off = 128; off > 0; off >>= 1) {
        if (t < off) red[t] += red[t + off];
        __syncthreads();
    }
    int base0 = red[0];

    // inclusive scan of tsum across the block
    for (int off = 1; off < 256; off <<= 1) {
        int a = (t >= off) ? sh[t - off] : 0;
        __syncthreads();
        sh[t] += a;
        __syncthreads();
    }
    int base = base0 + sh[t] - tsum;           // exclusive
    int4 o;
    o.x = base;
    o.y = o.x + c.x;
    o.z = o.y + c.y;
    o.w = o.z + c.z;
    reinterpret_cast<int4*>(g_row)[b * 256 + t] = o;
}

// Fused permute + init. Blocks [0, GE): place each edge at row[dst]+rank
// (no atomics). Blocks [GE, GE+98): finalize norms, stage rs0 = ns*w*x.
__global__ void k_permInit(int ge, const float* __restrict__ x) {
    if (blockIdx.x < (unsigned)ge) {
        int e = blockIdx.x * blockDim.x + threadIdx.x;
        if (e < EE) {
            int2 ed = g_edge[e];
            int d = ed.y & DMASK;
            int r = ((unsigned)ed.y) >> 17;
            g_sort[g_row[d] + r] = make_int2(ed.x, d);
        }
    } else {
        int n = (blockIdx.x - ge) * blockDim.x + threadIdx.x;
        if (n < NN / 4) {
            float w = g_scal[6];
            int4 cs = reinterpret_cast<const int4*>(g_cs)[n];
            int4 cd = reinterpret_cast<const int4*>(g_cd)[n];
            float4 xv = reinterpret_cast<const float4*>(x)[n];
            float4 ns, nd, rs;
            ns.x = rsqrtf(fmaxf((float)cs.x, 1.f)); nd.x = rsqrtf(fmaxf((float)cd.x, 1.f));
            ns.y = rsqrtf(fmaxf((float)cs.y, 1.f)); nd.y = rsqrtf(fmaxf((float)cd.y, 1.f));
            ns.z = rsqrtf(fmaxf((float)cs.z, 1.f)); nd.z = rsqrtf(fmaxf((float)cd.z, 1.f));
            ns.w = rsqrtf(fmaxf((float)cs.w, 1.f)); nd.w = rsqrtf(fmaxf((float)cd.w, 1.f));
            rs.x = ns.x * w * xv.x; rs.y = ns.y * w * xv.y;
            rs.z = ns.z * w * xv.z; rs.w = ns.w * w * xv.w;
            reinterpret_cast<float4*>(g_ns)[n] = ns;
            reinterpret_cast<float4*>(g_nd)[n] = nd;
            reinterpret_cast<float4*>(g_rs)[n] = rs;
        }
    }
}

// One propagation hop: 2 edges/thread pair-aggregated segmented reduction.
// dst-sorted ⇒ per pair d0<=d1 and prev.d1 <= d0. The 5-step shfl scan covers
// 64 edges per warp. Mid-pair run breaks (d0!=d1) flush v0 + neighbor prefix;
// run tails flush the scanned sum. ~150K atomics total.
__global__ void k_scatter() {
    int i = blockIdx.x * blockDim.x + threadIdx.x;
    if (i >= EE / 2) return;
    int4 q = reinterpret_cast<const int4*>(g_sort)[i];   // (s0,d0,s1,d1)
    float v0 = __ldg(&g_rs[q.x]);
    float v1 = __ldg(&g_rs[q.z]);
    int d0 = q.y, d1 = q.w;
    unsigned lane = threadIdx.x & 31;

    bool pairsame = (d0 == d1);
    float a = pairsame ? (v0 + v1) : v1;     // trailing-run (d1) contribution

    int d1prev = __shfl_up_sync(0xFFFFFFFFu, d1, 1);
    int d0next = __shfl_down_sync(0xFFFFFFFFu, d0, 1);

    // head of the scan chain over trailing runs
    bool head = (lane == 0) || (d1prev != d1) || !pairsame;
    unsigned hm = __ballot_sync(0xFFFFFFFFu, head);
    unsigned below = hm & ((2u << lane) - 1u);
    int start = 31 - __clz(below);

#pragma unroll
    for (int off = 1; off < 32; off <<= 1) {
        float u = __shfl_up_sync(0xFFFFFFFFu, a, off);
        if ((int)lane - off >= start) a += u;
    }
    // scanned prefix from previous lane (for mid-pair flush)
    float aprev = __shfl_up_sync(0xFFFFFFFFu, a, 1);

    // Mid-pair flush: d0's run ends at my first edge.
    if (!pairsame) {
        float sum0 = v0;
        if (lane > 0 && d1prev == d0) sum0 += aprev;
        atomicAdd(&g_acc[d0], sum0);
    }
    // Tail flush: nobody ahead carries my d1 run.
    bool tail = (lane == 31) || (d0next != d1);
    if (tail) atomicAdd(&g_acc[d1], a);
}

// r_{k+1} = nd*acc + s_k. k<5: stage rs = ns*r_{k+1}, re-zero acc.
// k==5: out = |r_6|. (float4)
__global__ void k_post(int k, float* __restrict__ out) {
    int n = blockIdx.x * blockDim.x + threadIdx.x;
    if (n < NN / 4) {
        float sk = g_scal[k];
        float4 nd = reinterpret_cast<float4*>(g_nd)[n];
        float4 ac = reinterpret_cast<float4*>(g_acc)[n];
        float4 v;
        v.x = nd.x * ac.x + sk;
        v.y = nd.y * ac.y + sk;
        v.z = nd.z * ac.z + sk;
        v.w = nd.w * ac.w + sk;
        if (k == 5) {
            float4 o;
            o.x = fabsf(v.x); o.y = fabsf(v.y);
            o.z = fabsf(v.z); o.w = fabsf(v.w);
            reinterpret_cast<float4*>(out)[n] = o;
        } else {
            float4 ns = reinterpret_cast<float4*>(g_ns)[n];
            float4 rs;
            rs.x = ns.x * v.x; rs.y = ns.y * v.y;
            rs.z = ns.z * v.z; rs.w = ns.w * v.w;
            reinterpret_cast<float4*>(g_rs)[n] = rs;
            reinterpret_cast<float4*>(g_acc)[n] = make_float4(0.f, 0.f, 0.f, 0.f);
        }
    }
}

extern "C" void kernel_launch(void* const* d_in, const int* in_sizes, int n_in,
                              void* d_out, int out_size) {
    // Layout A (dict order): x, src, dst, W0,b0..W5,b5
    // Layout B (sorted):     W0..W5, b0..b5, dst, src, x
    const float *x, *W0, *b0, *W1, *b1, *W2, *b2, *W3, *b3, *W4, *b4, *W5, *b5;
    const void *src, *dst;

    if (in_sizes[0] == NN) {
        x   = (const float*)d_in[0];
        src = d_in[1];
        dst = d_in[2];
        W0 = (const float*)d_in[3];  b0 = (const float*)d_in[4];
        W1 = (const float*)d_in[5];  b1 = (const float*)d_in[6];
        W2 = (const float*)d_in[7];  b2 = (const float*)d_in[8];
        W3 = (const float*)d_in[9];  b3 = (const float*)d_in[10];
        W4 = (const float*)d_in[11]; b4 = (const float*)d_in[12];
        W5 = (const float*)d_in[13]; b5 = (const float*)d_in[14];
    } else {
        W0 = (const float*)d_in[0];  W1 = (const float*)d_in[1];
        W2 = (const float*)d_in[2];  W3 = (const float*)d_in[3];
        W4 = (const float*)d_in[4];  W5 = (const float*)d_in[5];
        b0 = (const float*)d_in[6];  b1 = (const float*)d_in[7];
        b2 = (const float*)d_in[8];  b3 = (const float*)d_in[9];
        b4 = (const float*)d_in[10]; b5 = (const float*)d_in[11];
        dst = d_in[12];
        src = d_in[13];
        x   = (const float*)d_in[14];
    }
    float* out = (float*)d_out;

    const int TB  = 256;
    const int GZ  = NPAD / 4 / TB + 2;            // setup: 98 zero blocks + 2
    const int GN4 = (NN / 4 + TB - 1) / TB;       // 98
    const int GE  = (EE + TB - 1) / TB;           // 6250
    const int GS2 = (EE / 2 + TB - 1) / TB;       // 3125

    k_setup<<<GZ, TB>>>((const unsigned long long*)src,
                        W0, b0, W1, b1, W2, b2, W3, b3, W4, b4, W5, b5);
    k_edges<<<GE, TB>>>(src, dst);
    k_scan<<<98, TB>>>();
    k_permInit<<<GE + GN4, TB>>>(GE, x);

    for (int k = 0; k < 6; k++) {
        k_scatter<<<GS2, TB>>>();
        k_post<<<GN4, TB>>>(k, out);
    }
}